// round 7
// baseline (speedup 1.0000x reference)
#include <cuda_runtime.h>
#include <cuda_bf16.h>
#include <math.h>

#define BB 32
#define TT 2048
#define DD 256
#define HH 128
#define PITCH 40          // padded chunk pitch (floats): conflict-free quad reads

// Scratch
__device__ float g_xp0[(size_t)TT * BB * HH];   // layer-0 pre-activation (bias folded)
__device__ float g_h0 [(size_t)TT * BB * HH];   // layer-0 hidden stream
// progress flags, padded to one 128B line per batch element (zero-initialized)
__device__ volatile int g_flag [BB * 32];
__device__ volatile int g_start[BB * 32];

// tanh via MUFU.EX2 + MUFU.RCP: abs err ~1e-7, overflow-safe
__device__ __forceinline__ float fast_tanh(float x) {
    float ax = fabsf(x);
    float e  = __expf(-2.0f * ax);
    float r  = __fdividef(1.0f - e, 1.0f + e);
    return copysignf(r, x);
}

// ---------------------------------------------------------------------------
// GEMM (round-6, FMA-shaped): xp0[t][b][j] = x[b][t][:].W_ih0[j][:] + biases
// ---------------------------------------------------------------------------
__global__ __launch_bounds__(128) void gemm0_kernel(
    const float* __restrict__ x,
    const float* __restrict__ W_ih0,
    const float* __restrict__ b_ih0,
    const float* __restrict__ b_hh0)
{
    __shared__ float ws[64][HH];
    __shared__ float xs[64][33];

    const int t    = blockIdx.x;
    const int tid  = threadIdx.x;
    const int lane = tid & 31;
    const int w    = tid >> 5;
    const int jg   = lane * 4;
    const int bg   = w * 8;

    float acc[8][4];
#pragma unroll
    for (int i = 0; i < 8; i++)
#pragma unroll
        for (int q = 0; q < 4; q++) acc[i][q] = 0.f;

    for (int k0 = 0; k0 < DD; k0 += 64) {
        for (int i = tid; i < BB * 16; i += 128) {
            int b  = i >> 4;
            int kk = (i & 15) * 4;
            float4 v = *(const float4*)&x[((size_t)b * TT + t) * DD + k0 + kk];
            xs[kk + 0][b] = v.x; xs[kk + 1][b] = v.y;
            xs[kk + 2][b] = v.z; xs[kk + 3][b] = v.w;
        }
        for (int i = tid; i < HH * 16; i += 128) {
            int j  = i >> 4;
            int kk = (i & 15) * 4;
            float4 wv = *(const float4*)&W_ih0[(size_t)j * DD + k0 + kk];
            ws[kk + 0][j] = wv.x; ws[kk + 1][j] = wv.y;
            ws[kk + 2][j] = wv.z; ws[kk + 3][j] = wv.w;
        }
        __syncthreads();

#pragma unroll 8
        for (int k = 0; k < 64; k++) {
            float4 wv = *(const float4*)&ws[k][jg];
            float xv[8];
#pragma unroll
            for (int i = 0; i < 8; i++) xv[i] = xs[k][bg + i];
#pragma unroll
            for (int i = 0; i < 8; i++) {
                acc[i][0] += wv.x * xv[i];
                acc[i][1] += wv.y * xv[i];
                acc[i][2] += wv.z * xv[i];
                acc[i][3] += wv.w * xv[i];
            }
        }
        __syncthreads();
    }

    float4 bias;
    bias.x = b_ih0[jg + 0] + b_hh0[jg + 0];
    bias.y = b_ih0[jg + 1] + b_hh0[jg + 1];
    bias.z = b_ih0[jg + 2] + b_hh0[jg + 2];
    bias.w = b_ih0[jg + 3] + b_hh0[jg + 3];

#pragma unroll
    for (int i = 0; i < 8; i++) {
        float4 o;
        o.x = acc[i][0] + bias.x;
        o.y = acc[i][1] + bias.y;
        o.z = acc[i][2] + bias.z;
        o.w = acc[i][3] + bias.w;
        *(float4*)&g_xp0[((size_t)t * BB + bg + i) * HH + jg] = o;
    }
}

// ---------------------------------------------------------------------------
// Fused pipelined recurrences. grid = 64, block = 1024.
// bid<32: L0 producer (batch bid). bid>=32: L1 consumer (batch bid-32).
// ---------------------------------------------------------------------------
__global__ void __launch_bounds__(1024, 1) fused_rec_kernel(
    const float* __restrict__ W_hh0,
    const float* __restrict__ W_ih1,
    const float* __restrict__ W_hh1,
    const float* __restrict__ b_ih1,
    const float* __restrict__ b_hh1,
    float* __restrict__ out)
{
    const int bid = blockIdx.x;
    const int tid = threadIdx.x;

    if (bid < BB) {
        // ================= L0 producer =================
        const int b  = bid;
        const int lt = tid & 511;
        const int j  = lt >> 2;
        const int c  = lt & 3;

        __shared__ __align__(16) float hbuf[2][4 * PITCH];

        // reset flag, then open the gate for this launch
        if (tid == 512) {
            g_flag[b * 32] = 0;
            __threadfence();
            g_start[b * 32] = 1;
        }

        float4 w[8];
        if (tid < 512) {
            const float4* p = (const float4*)&W_hh0[(size_t)j * HH + c * 32];
#pragma unroll
            for (int i = 0; i < 8; i++) w[i] = p[i];
        }
        for (int i = tid; i < 2 * 4 * PITCH; i += 1024)
            ((float*)hbuf)[i] = 0.f;
        __syncthreads();

        const int posj = (j >> 5) * PITCH + (j & 31);
        const float* zp = g_xp0 + (size_t)b * HH + j;
        float z0 = 0.f, z1 = 0.f;
        if (tid < 512) {
            z0 = zp[0];
            z1 = zp[(size_t)BB * HH];
            zp += (size_t)2 * BB * HH;
        }

        for (int t = 0; t < TT; t++) {
            if (tid < 512) {
                const int p = t & 1;
                const float4* hrd = (const float4*)&hbuf[p][c * PITCH];
                float aa = 0.f, ab = 0.f;
#pragma unroll
                for (int i = 0; i < 8; i++) {
                    float4 h = hrd[i];
                    aa += w[i].x * h.x + w[i].y * h.y;
                    ab += w[i].z * h.z + w[i].w * h.w;
                }
                float a = aa + ab;
                a += __shfl_xor_sync(0xFFFFFFFFu, a, 1);
                a += __shfl_xor_sync(0xFFFFFFFFu, a, 2);

                float hn = fast_tanh(z0 + a);
                hbuf[1 - p][posj] = hn;
                if (c == 0)
                    g_h0[((size_t)t * BB + b) * HH + j] = hn;

                z0 = z1;
                if (t + 2 < TT) {
                    z1 = *zp;
                    zp += (size_t)BB * HH;
                }
            }
            __syncthreads();
            // publish step t (ordered after all STGs via barrier + cumulative fence)
            if (tid == 512) {
                __threadfence();
                g_flag[b * 32] = t + 1;
            }
        }
    } else {
        // ================= L1 consumer =================
        const int b    = bid - BB;
        const int half = tid >> 9;          // 0 = serial (B), 1 = parallel (A)
        const int lt   = tid & 511;
        const int j    = lt >> 2;
        const int c    = lt & 3;

        __shared__ __align__(16) float h1buf[2][4 * PITCH];
        __shared__ float sbuf[2][HH];
        __shared__ __align__(16) float ring[4][4 * PITCH];

        float4 w[8];
        {
            const float* W = (half == 0) ? W_hh1 : W_ih1;
            const float4* p = (const float4*)&W[(size_t)j * HH + c * 32];
#pragma unroll
            for (int i = 0; i < 8; i++) w[i] = p[i];
        }
        const int   posj  = (j >> 5) * PITCH + (j & 31);
        const float biasj = b_ih1[j] + b_hh1[j];

        for (int i = tid; i < 2 * 4 * PITCH; i += 1024)
            ((float*)h1buf)[i] = 0.f;

        // loader warp primes ring slots 0..2 (h0[0..2])
        if (tid >= 512 && tid < 544) {
            const int l = tid - 512;            // 0..31, handles 16B
            while (g_start[b * 32] == 0) {}
            __threadfence();
            for (int s = 0; s < 3; s++) {
                while (g_flag[b * 32] < s + 1) {}
                __threadfence();
                float4 v = *(const float4*)&g_h0[((size_t)s * BB + b) * HH + l * 4];
                *(float4*)&ring[s][((l * 4) >> 5) * PITCH + ((l * 4) & 31)] = v;
            }
        }
        __syncthreads();

        // A computes s_ih[0]
        if (half == 1) {
            const float4* hr = (const float4*)&ring[0][c * PITCH];
            float aa = 0.f, ab = 0.f;
#pragma unroll
            for (int i = 0; i < 8; i++) {
                float4 h = hr[i];
                aa += w[i].x * h.x + w[i].y * h.y;
                ab += w[i].z * h.z + w[i].w * h.w;
            }
            float s = aa + ab;
            s += __shfl_xor_sync(0xFFFFFFFFu, s, 1);
            s += __shfl_xor_sync(0xFFFFFFFFu, s, 2);
            sbuf[0][j] = s;
        }
        __syncthreads();

        float* outb = out + (size_t)b * TT * HH;

        for (int t = 0; t < TT; t++) {
            if (half == 0) {
                // serial chain: one matvec + tanh
                const int p = t & 1;
                const float4* hrd = (const float4*)&h1buf[p][c * PITCH];
                float aa = 0.f, ab = 0.f;
#pragma unroll
                for (int i = 0; i < 8; i++) {
                    float4 h = hrd[i];
                    aa += w[i].x * h.x + w[i].y * h.y;
                    ab += w[i].z * h.z + w[i].w * h.w;
                }
                float a = aa + ab;
                a += __shfl_xor_sync(0xFFFFFFFFu, a, 1);
                a += __shfl_xor_sync(0xFFFFFFFFu, a, 2);

                float hn = fast_tanh(a + sbuf[t & 1][j] + biasj);
                h1buf[1 - p][posj] = hn;
                if (c == 0)
                    outb[(size_t)t * HH + j] = hn;
            } else {
                // parallel term for step t+1
                if (t + 1 < TT) {
                    const float4* hr = (const float4*)&ring[(t + 1) & 3][c * PITCH];
                    float aa = 0.f, ab = 0.f;
#pragma unroll
                    for (int i = 0; i < 8; i++) {
                        float4 h = hr[i];
                        aa += w[i].x * h.x + w[i].y * h.y;
                        ab += w[i].z * h.z + w[i].w * h.w;
                    }
                    float s = aa + ab;
                    s += __shfl_xor_sync(0xFFFFFFFFu, s, 1);
                    s += __shfl_xor_sync(0xFFFFFFFFu, s, 2);
                    sbuf[(t + 1) & 1][j] = s;
                }
                // loader warp fetches h0[t+3] (2 steps of slack)
                if (tid < 544 && t + 3 < TT) {
                    const int l = tid - 512;
                    while (g_flag[b * 32] < t + 4) {}
                    __threadfence();
                    float4 v = *(const float4*)&g_h0[((size_t)(t + 3) * BB + b) * HH + l * 4];
                    *(float4*)&ring[(t + 3) & 3][((l * 4) >> 5) * PITCH + ((l * 4) & 31)] = v;
                }
            }
            __syncthreads();
        }

        // close the gate for the next launch
        if (tid == 512) {
            __threadfence();
            g_start[b * 32] = 0;
        }
    }
}

// ---------------------------------------------------------------------------
extern "C" void kernel_launch(void* const* d_in, const int* in_sizes, int n_in,
                              void* d_out, int out_size)
{
    const float* x     = (const float*)d_in[0];
    const float* W_ih0 = (const float*)d_in[1];
    const float* W_hh0 = (const float*)d_in[2];
    const float* b_ih0 = (const float*)d_in[3];
    const float* b_hh0 = (const float*)d_in[4];
    const float* W_ih1 = (const float*)d_in[5];
    const float* W_hh1 = (const float*)d_in[6];
    const float* b_ih1 = (const float*)d_in[7];
    const float* b_hh1 = (const float*)d_in[8];
    float* out = (float*)d_out;

    gemm0_kernel<<<TT, 128>>>(x, W_ih0, b_ih0, b_hh0);
    fused_rec_kernel<<<2 * BB, 1024>>>(W_hh0, W_ih1, W_hh1, b_ih1, b_hh1, out);
}

// round 9
// speedup vs baseline: 1.3403x; 1.3403x over previous
#include <cuda_runtime.h>
#include <cuda_bf16.h>
#include <math.h>

#define BB 32
#define TT 2048
#define DD 256
#define HH 128
#define PITCH 40      // quad-chunk pitch (floats): banks 0/8/16/24 -> conflict-free
#define H1P   72      // half-chunk pitch for h1 (floats): banks 0/8 -> conflict-free

// Scratch: layer-0 pre-activation stream (bias folded), [t][b][h]
__device__ float g_xp0[(size_t)TT * BB * HH];

// tanh via MUFU.EX2 + MUFU.RCP: abs err ~1e-7, overflow-safe (e->0 => r->1)
__device__ __forceinline__ float fast_tanh(float x) {
    float ax = fabsf(x);
    float e  = __expf(-2.0f * ax);
    float r  = __fdividef(1.0f - e, 1.0f + e);
    return copysignf(r, x);
}

// ---------------------------------------------------------------------------
// GEMM (FMA-shaped): xp0[t][b][j] = x[b][t][:].W_ih0[j][:] + b_ih0[j]+b_hh0[j]
// ---------------------------------------------------------------------------
__global__ __launch_bounds__(128) void gemm0_kernel(
    const float* __restrict__ x,
    const float* __restrict__ W_ih0,
    const float* __restrict__ b_ih0,
    const float* __restrict__ b_hh0)
{
    __shared__ float ws[64][HH];
    __shared__ float xs[64][33];

    const int t    = blockIdx.x;
    const int tid  = threadIdx.x;
    const int lane = tid & 31;
    const int w    = tid >> 5;
    const int jg   = lane * 4;
    const int bg   = w * 8;

    float acc[8][4];
#pragma unroll
    for (int i = 0; i < 8; i++)
#pragma unroll
        for (int q = 0; q < 4; q++) acc[i][q] = 0.f;

    for (int k0 = 0; k0 < DD; k0 += 64) {
        for (int i = tid; i < BB * 16; i += 128) {
            int b  = i >> 4;
            int kk = (i & 15) * 4;
            float4 v = *(const float4*)&x[((size_t)b * TT + t) * DD + k0 + kk];
            xs[kk + 0][b] = v.x; xs[kk + 1][b] = v.y;
            xs[kk + 2][b] = v.z; xs[kk + 3][b] = v.w;
        }
        for (int i = tid; i < HH * 16; i += 128) {
            int j  = i >> 4;
            int kk = (i & 15) * 4;
            float4 wv = *(const float4*)&W_ih0[(size_t)j * DD + k0 + kk];
            ws[kk + 0][j] = wv.x; ws[kk + 1][j] = wv.y;
            ws[kk + 2][j] = wv.z; ws[kk + 3][j] = wv.w;
        }
        __syncthreads();

#pragma unroll 8
        for (int k = 0; k < 64; k++) {
            float4 wv = *(const float4*)&ws[k][jg];
            float xv[8];
#pragma unroll
            for (int i = 0; i < 8; i++) xv[i] = xs[k][bg + i];
#pragma unroll
            for (int i = 0; i < 8; i++) {
                acc[i][0] += wv.x * xv[i];
                acc[i][1] += wv.y * xv[i];
                acc[i][2] += wv.z * xv[i];
                acc[i][3] += wv.w * xv[i];
            }
        }
        __syncthreads();
    }

    float4 bias;
    bias.x = b_ih0[jg + 0] + b_hh0[jg + 0];
    bias.y = b_ih0[jg + 1] + b_hh0[jg + 1];
    bias.z = b_ih0[jg + 2] + b_hh0[jg + 2];
    bias.w = b_ih0[jg + 3] + b_hh0[jg + 3];

#pragma unroll
    for (int i = 0; i < 8; i++) {
        float4 o;
        o.x = acc[i][0] + bias.x;
        o.y = acc[i][1] + bias.y;
        o.z = acc[i][2] + bias.z;
        o.w = acc[i][3] + bias.w;
        *(float4*)&g_xp0[((size_t)t * BB + bg + i) * HH + jg] = o;
    }
}

// ---------------------------------------------------------------------------
// Fused 2-layer recurrence, one CTA per batch, 768 threads, ONE barrier/phase.
// Phase t (t = 0 .. TT+1):
//   quad half (tid<512, tid=j*4+c), reads h0[t-1] and z[t] from smem:
//     a0 = W_hh0[j].h0[t-1] -> h0[t] = tanh(z[t]+a0)      (c==0 writes)
//     a1 = W_ih1[j].h0[t-1] -> s_ih[t-1] = a1             (c==1 writes)
//   pair half (tid>=512, lt=j2*2+c2):
//     a2 = W_hh1[j2].h1[t-3] -> h1[t-2] = tanh(s_ih[t-2]+a2+bias)
//                               (c2==0 writes smem + out)
//   z pipeline (pair half, lt<128): STS z[t+3] (reg) ; LDG z[t+4] -> reg.
// All reads come from previous phases (parity/mod-4 buffered). Output lags 2.
// ---------------------------------------------------------------------------
__global__ void __launch_bounds__(768, 1) fused2_kernel(
    const float* __restrict__ W_hh0,
    const float* __restrict__ W_ih1,
    const float* __restrict__ W_hh1,
    const float* __restrict__ b_ih1,
    const float* __restrict__ b_hh1,
    float* __restrict__ out)
{
    const int b   = blockIdx.x;
    const int tid = threadIdx.x;

    __shared__ __align__(16) float h0buf[2][4 * PITCH];
    __shared__ __align__(16) float h1buf[2][2 * H1P];
    __shared__ float sih[2][HH];
    __shared__ float zbuf[4][HH];

    // zero recurrent state
    for (int i = tid; i < 2 * 4 * PITCH; i += 768) ((float*)h0buf)[i] = 0.f;
    for (int i = tid; i < 2 * 2 * H1P;   i += 768) ((float*)h1buf)[i] = 0.f;
    for (int i = tid; i < 2 * HH;        i += 768) ((float*)sih)[i]   = 0.f;

    // per-half setup
    float4 wA[8], wB[8];
    int   posj = 0, j = 0, c = 0, j2 = 0, c2 = 0;
    float biasj = 0.f;
    float zr = 0.f;                      // z pipeline register (pair, lt<128)
    const float* zp = nullptr;
    float* outb = out + (size_t)b * TT * HH;

    if (tid < 512) {
        j = tid >> 2; c = tid & 3;
        const float4* p0 = (const float4*)&W_hh0[(size_t)j * HH + c * 32];
        const float4* p1 = (const float4*)&W_ih1[(size_t)j * HH + c * 32];
#pragma unroll
        for (int i = 0; i < 8; i++) { wA[i] = p0[i]; wB[i] = p1[i]; }
        posj = (j >> 5) * PITCH + (j & 31);
    } else {
        int lt = tid - 512;              // 0..255
        j2 = lt >> 1; c2 = lt & 1;
        const float4* p0 = (const float4*)&W_hh1[(size_t)j2 * HH + c2 * 64];
        const float4* p1 = (const float4*)&W_hh1[(size_t)j2 * HH + c2 * 64 + 32];
#pragma unroll
        for (int i = 0; i < 8; i++) { wA[i] = p0[i]; wB[i] = p1[i]; }
        posj = (j2 >> 6) * H1P + (j2 & 63);
        biasj = b_ih1[j2] + b_hh1[j2];

        // z pipeline prime: slots 0..2 <- z[0..2]; zr <- z[3]
        if (lt < HH) {
            zp = g_xp0 + (size_t)b * HH + lt;
            zbuf[0][lt] = zp[0];
            zbuf[1][lt] = zp[(size_t)1 * BB * HH];
            zbuf[2][lt] = zp[(size_t)2 * BB * HH];
            zr          = zp[(size_t)3 * BB * HH];
            zp += (size_t)4 * BB * HH;
        }
    }
    __syncthreads();

    for (int t = 0; t < TT + 2; t++) {
        const int p  = t & 1;
        const int rd = 1 - p;

        if (tid < 512) {
            // ---- layer-0 matvec + layer-1 input matvec (same h0[t-1]) ----
            const float4* hrd = (const float4*)&h0buf[rd][c * PITCH];
            float aa = 0.f, ab = 0.f, ba = 0.f, bb2 = 0.f;
#pragma unroll
            for (int i = 0; i < 8; i++) {
                float4 h = hrd[i];
                aa  += wA[i].x * h.x + wA[i].y * h.y;
                ab  += wA[i].z * h.z + wA[i].w * h.w;
                ba  += wB[i].x * h.x + wB[i].y * h.y;
                bb2 += wB[i].z * h.z + wB[i].w * h.w;
            }
            float a0 = aa + ab;
            float a1 = ba + bb2;
            a0 += __shfl_xor_sync(0xFFFFFFFFu, a0, 1);
            a0 += __shfl_xor_sync(0xFFFFFFFFu, a0, 2);
            a1 += __shfl_xor_sync(0xFFFFFFFFu, a1, 1);
            a1 += __shfl_xor_sync(0xFFFFFFFFu, a1, 2);

            if (c == 0 && t < TT)
                h0buf[p][posj] = fast_tanh(zbuf[t & 3][j] + a0);   // h0[t]
            if (c == 1 && t >= 1 && t <= TT)
                sih[p][j] = a1;                                    // s_ih[t-1]
        } else {
            if (t >= 2) {
                // ---- layer-1 hidden matvec: W_hh1 . h1[t-3] ----
                const float4* hr0 = (const float4*)&h1buf[rd][c2 * H1P];
                const float4* hr1 = (const float4*)&h1buf[rd][c2 * H1P + 32];
                float s0 = 0.f, s1 = 0.f, s2 = 0.f, s3 = 0.f;
#pragma unroll
                for (int i = 0; i < 8; i++) {
                    float4 h = hr0[i];
                    s0 += wA[i].x * h.x + wA[i].y * h.y;
                    s1 += wA[i].z * h.z + wA[i].w * h.w;
                    float4 g = hr1[i];
                    s2 += wB[i].x * g.x + wB[i].y * g.y;
                    s3 += wB[i].z * g.z + wB[i].w * g.w;
                }
                float a2 = (s0 + s1) + (s2 + s3);
                a2 += __shfl_xor_sync(0xFFFFFFFFu, a2, 1);

                float h1n = fast_tanh(sih[rd][j2] + a2 + biasj);   // h1[t-2]
                if (c2 == 0) {
                    h1buf[p][posj] = h1n;
                    outb[(size_t)(t - 2) * HH + j2] = h1n;
                }
            }
            // ---- z pipeline: publish z[t+3], fetch z[t+4] ----
            if (tid - 512 < HH) {
                zbuf[(t + 3) & 3][tid - 512] = zr;                 // z[t+3]
                if (t + 4 < TT) {
                    zr = *zp;                                      // z[t+4]
                    zp += (size_t)BB * HH;
                }
            }
        }

        __syncthreads();
    }
}

// ---------------------------------------------------------------------------
extern "C" void kernel_launch(void* const* d_in, const int* in_sizes, int n_in,
                              void* d_out, int out_size)
{
    const float* x     = (const float*)d_in[0];
    const float* W_ih0 = (const float*)d_in[1];
    const float* W_hh0 = (const float*)d_in[2];
    const float* b_ih0 = (const float*)d_in[3];
    const float* b_hh0 = (const float*)d_in[4];
    const float* W_ih1 = (const float*)d_in[5];
    const float* W_hh1 = (const float*)d_in[6];
    const float* b_ih1 = (const float*)d_in[7];
    const float* b_hh1 = (const float*)d_in[8];
    float* out = (float*)d_out;

    gemm0_kernel<<<TT, 128>>>(x, W_ih0, b_ih0, b_hh0);
    fused2_kernel<<<BB, 768>>>(W_hh0, W_ih1, W_hh1, b_ih1, b_hh1, out);
}

// round 11
// speedup vs baseline: 1.9253x; 1.4364x over previous
#include <cuda_runtime.h>
#include <cuda_bf16.h>
#include <math.h>

#define BB 32
#define TT 2048
#define DD 256
#define HH 128

// Scratch: layer-0 pre-activation stream (bias folded), [t][b][h]
__device__ float g_xp0[(size_t)TT * BB * HH];

// tanh via MUFU.EX2 + MUFU.RCP: abs err ~1e-7, overflow-safe (e->0 => r->1)
__device__ __forceinline__ float fast_tanh(float x) {
    float ax = fabsf(x);
    float e  = __expf(-2.0f * ax);
    float r  = __fdividef(1.0f - e, 1.0f + e);
    return copysignf(r, x);
}

// ---------------------------------------------------------------------------
// GEMM (FMA-shaped): xp0[t][b][j] = x[b][t][:].W_ih0[j][:] + b_ih0[j]+b_hh0[j]
// One block per t, 128 threads; thread tile 4 j x 8 b; weights one lane-
// distinct float4/k, x broadcast scalars -> FMA-port bound.
// ---------------------------------------------------------------------------
__global__ __launch_bounds__(128) void gemm0_kernel(
    const float* __restrict__ x,
    const float* __restrict__ W_ih0,
    const float* __restrict__ b_ih0,
    const float* __restrict__ b_hh0)
{
    __shared__ float ws[64][HH];
    __shared__ float xs[64][33];

    const int t    = blockIdx.x;
    const int tid  = threadIdx.x;
    const int lane = tid & 31;
    const int w    = tid >> 5;
    const int jg   = lane * 4;
    const int bg   = w * 8;

    float acc[8][4];
#pragma unroll
    for (int i = 0; i < 8; i++)
#pragma unroll
        for (int q = 0; q < 4; q++) acc[i][q] = 0.f;

    for (int k0 = 0; k0 < DD; k0 += 64) {
        for (int i = tid; i < BB * 16; i += 128) {
            int b  = i >> 4;
            int kk = (i & 15) * 4;
            float4 v = *(const float4*)&x[((size_t)b * TT + t) * DD + k0 + kk];
            xs[kk + 0][b] = v.x; xs[kk + 1][b] = v.y;
            xs[kk + 2][b] = v.z; xs[kk + 3][b] = v.w;
        }
        for (int i = tid; i < HH * 16; i += 128) {
            int j  = i >> 4;
            int kk = (i & 15) * 4;
            float4 wv = *(const float4*)&W_ih0[(size_t)j * DD + k0 + kk];
            ws[kk + 0][j] = wv.x; ws[kk + 1][j] = wv.y;
            ws[kk + 2][j] = wv.z; ws[kk + 3][j] = wv.w;
        }
        __syncthreads();

#pragma unroll 8
        for (int k = 0; k < 64; k++) {
            float4 wv = *(const float4*)&ws[k][jg];
            float xv[8];
#pragma unroll
            for (int i = 0; i < 8; i++) xv[i] = xs[k][bg + i];
#pragma unroll
            for (int i = 0; i < 8; i++) {
                acc[i][0] += wv.x * xv[i];
                acc[i][1] += wv.y * xv[i];
                acc[i][2] += wv.z * xv[i];
                acc[i][3] += wv.w * xv[i];
            }
        }
        __syncthreads();
    }

    float4 bias;
    bias.x = b_ih0[jg + 0] + b_hh0[jg + 0];
    bias.y = b_ih0[jg + 1] + b_hh0[jg + 1];
    bias.z = b_ih0[jg + 2] + b_hh0[jg + 2];
    bias.w = b_ih0[jg + 3] + b_hh0[jg + 3];

#pragma unroll
    for (int i = 0; i < 8; i++) {
        float4 o;
        o.x = acc[i][0] + bias.x;
        o.y = acc[i][1] + bias.y;
        o.z = acc[i][2] + bias.z;
        o.w = acc[i][3] + bias.w;
        *(float4*)&g_xp0[((size_t)t * BB + bg + i) * HH + jg] = o;
    }
}

// ---------------------------------------------------------------------------
// Fused 2-layer recurrence, one CTA per batch, 512 threads, round-1 layout:
// tid = c*128 + j  (c = tid>>7 in 0..3 is a 32-wide k-chunk, j = output).
// ONE compute phase per step via output lag:
//   invariant at step t entry: h0s = h0[t-1], h1s = h1[t-2]
//   phase A (all threads): ps0 = part(W_hh0.h0[t-1]), ps1 = part(W_ih1.h0[t-1]),
//                          ps2 = part(W_hh1.h1[t-2])   [3 broadcast-LDS matvecs]
//   phase R: tid<128:        h0s[j] = tanh(z[t] + sum ps0)          = h0[t]
//            tid in[128,256): h1s[j] = tanh(sum ps1 + sum ps2 + bias) = h1[t-1]
//                             -> STG out[b][t-1][j]
// 2 barriers/step, fast_tanh, z prefetched ~2.5 steps deep in registers.
// ---------------------------------------------------------------------------
__global__ void __launch_bounds__(512, 1) fused_lag_kernel(
    const float* __restrict__ W_hh0,
    const float* __restrict__ W_ih1,
    const float* __restrict__ W_hh1,
    const float* __restrict__ b_ih1,
    const float* __restrict__ b_hh1,
    float* __restrict__ out)
{
    const int b   = blockIdx.x;
    const int tid = threadIdx.x;
    const int j   = tid & 127;
    const int c   = tid >> 7;

    __shared__ __align__(16) float h0s[HH];
    __shared__ __align__(16) float h1s[HH];
    __shared__ float ps0[4][HH];
    __shared__ float ps1[4][HH];
    __shared__ float ps2[4][HH];

    // register-stationary weights: chunk [c*32, c*32+32) of row j
    float4 w0[8], w1[8], w2[8];
    {
        const float4* p0 = (const float4*)&W_hh0[(size_t)j * HH + c * 32];
        const float4* p1 = (const float4*)&W_ih1[(size_t)j * HH + c * 32];
        const float4* p2 = (const float4*)&W_hh1[(size_t)j * HH + c * 32];
#pragma unroll
        for (int i = 0; i < 8; i++) { w0[i] = p0[i]; w1[i] = p1[i]; w2[i] = p2[i]; }
    }

    if (tid < HH) { h0s[tid] = 0.f; h1s[tid] = 0.f; }

    // h1-path bias (threads 128..255)
    float biasj = 0.f;
    if (tid >= 128 && tid < 256) biasj = b_ih1[j] + b_hh1[j];

    // z prefetch pipeline (h0-path threads only): z0=z[t], z1=z[t+1]
    const float* zp = g_xp0 + (size_t)b * HH + j;
    float z0 = 0.f, z1 = 0.f, znext = 0.f;
    if (tid < 128) {
        z0 = zp[0];
        z1 = zp[(size_t)BB * HH];
        zp += (size_t)2 * BB * HH;
    }

    // h1-path output pointer, advanced by stride each step
    float* op = out + (size_t)b * TT * HH + j;

    const float4* h0v = (const float4*)&h0s[c * 32];
    const float4* h1v = (const float4*)&h1s[c * 32];

    __syncthreads();

    for (int t = 0; t <= TT; t++) {
        // ---- phase A: issue z[t+2] load first (off-chain), then 3 matvecs ----
        if (tid < 128 && t + 2 < TT) {
            znext = *zp;
            zp += (size_t)BB * HH;
        }

        float a0 = 0.f, a1 = 0.f, a2 = 0.f;
#pragma unroll
        for (int i = 0; i < 8; i++) {
            float4 h = h0v[i];   // broadcast within warp
            a0 = fmaf(w0[i].x, h.x, a0); a0 = fmaf(w0[i].y, h.y, a0);
            a0 = fmaf(w0[i].z, h.z, a0); a0 = fmaf(w0[i].w, h.w, a0);
            a1 = fmaf(w1[i].x, h.x, a1); a1 = fmaf(w1[i].y, h.y, a1);
            a1 = fmaf(w1[i].z, h.z, a1); a1 = fmaf(w1[i].w, h.w, a1);
            float4 g = h1v[i];
            a2 = fmaf(w2[i].x, g.x, a2); a2 = fmaf(w2[i].y, g.y, a2);
            a2 = fmaf(w2[i].z, g.z, a2); a2 = fmaf(w2[i].w, g.w, a2);
        }
        ps0[c][j] = a0;
        ps1[c][j] = a1;
        ps2[c][j] = a2;
        __syncthreads();

        // ---- phase R ----
        if (tid < 128) {
            if (t < TT) {
                float s = z0 + ps0[0][j] + ps0[1][j] + ps0[2][j] + ps0[3][j];
                h0s[j] = fast_tanh(s);       // h0[t]
            }
            z0 = z1;
            z1 = znext;
        } else if (tid < 256) {
            if (t >= 1) {
                float s = ps1[0][j] + ps1[1][j] + ps1[2][j] + ps1[3][j]
                        + ps2[0][j] + ps2[1][j] + ps2[2][j] + ps2[3][j] + biasj;
                float h1n = fast_tanh(s);    // h1[t-1]
                h1s[j] = h1n;
                *op = h1n;
                op += HH;
            }
        }
        __syncthreads();
    }
}

// ---------------------------------------------------------------------------
extern "C" void kernel_launch(void* const* d_in, const int* in_sizes, int n_in,
                              void* d_out, int out_size)
{
    const float* x     = (const float*)d_in[0];
    const float* W_ih0 = (const float*)d_in[1];
    const float* W_hh0 = (const float*)d_in[2];
    const float* b_ih0 = (const float*)d_in[3];
    const float* b_hh0 = (const float*)d_in[4];
    const float* W_ih1 = (const float*)d_in[5];
    const float* W_hh1 = (const float*)d_in[6];
    const float* b_ih1 = (const float*)d_in[7];
    const float* b_hh1 = (const float*)d_in[8];
    float* out = (float*)d_out;

    gemm0_kernel<<<TT, 128>>>(x, W_ih0, b_ih0, b_hh0);
    fused_lag_kernel<<<BB, 512>>>(W_hh0, W_ih1, W_hh1, b_ih1, b_hh1, out);
}